// round 5
// baseline (speedup 1.0000x reference)
#include <cuda_runtime.h>
#include <cuda_bf16.h>
#include <cstdint>

#define N_NODES 100000
#define DIM     128
#define NREL    8
#define NEDGES  625000
#define NMAT    9
#define MTILE   64
#define NTILE   1563                 // ceil(N_NODES/64)
#define NKEY    (NTILE * 3)          // (tile, rel-group) buckets
#define NCHUNK  (NMAT * 8)           // 72 B chunks of 8KB

// ---------------------------------------------------------------------------
// Device globals
// ---------------------------------------------------------------------------
__device__ uint32_t g_wB[NMAT * 8 * 2048];   // pre-packed B frags (576 KB)
__device__ int      g_deg[N_NODES * NREL];
__device__ float    g_inv[N_NODES * NREL];
__device__ int      g_is32;
__device__ int      g_hist[NKEY];
__device__ int      g_off[NKEY + 1];
__device__ int      g_cursor[NKEY];
__device__ uint2    g_esort[NEDGES];         // {packed(src,ri,dl), scale}

// ---------------------------------------------------------------------------
// helpers
// ---------------------------------------------------------------------------
__device__ __forceinline__ uint32_t smem_u32(const void* p) {
    uint32_t a;
    asm("{ .reg .u64 t; cvta.to.shared.u64 t, %1; cvt.u32.u64 %0, t; }"
        : "=r"(a) : "l"(p));
    return a;
}
__device__ __forceinline__ uint32_t pack_bf2(__nv_bfloat16 lo, __nv_bfloat16 hi) {
    return (uint32_t)__bfloat16_as_ushort(lo) | ((uint32_t)__bfloat16_as_ushort(hi) << 16);
}
__device__ __forceinline__ void split2(float2 v, uint32_t& h, uint32_t& l) {
    __nv_bfloat16 h0 = __float2bfloat16(v.x);
    __nv_bfloat16 h1 = __float2bfloat16(v.y);
    __nv_bfloat16 l0 = __float2bfloat16(v.x - __bfloat162float(h0));
    __nv_bfloat16 l1 = __float2bfloat16(v.y - __bfloat162float(h1));
    h = pack_bf2(h0, h1);
    l = pack_bf2(l0, l1);
}
__device__ __forceinline__ void mma_bf16(float* c, uint32_t a0, uint32_t a1,
                                         uint32_t a2, uint32_t a3,
                                         uint32_t b0, uint32_t b1) {
    asm volatile(
        "mma.sync.aligned.m16n8k16.row.col.f32.bf16.bf16.f32 "
        "{%0,%1,%2,%3}, {%4,%5,%6,%7}, {%8,%9}, {%0,%1,%2,%3};"
        : "+f"(c[0]), "+f"(c[1]), "+f"(c[2]), "+f"(c[3])
        : "r"(a0), "r"(a1), "r"(a2), "r"(a3), "r"(b0), "r"(b1));
}
__device__ __forceinline__ void cp16(uint32_t smem_dst, const void* gsrc) {
    asm volatile("cp.async.cg.shared.global [%0], [%1], 16;"
                 :: "r"(smem_dst), "l"(gsrc));
}
__device__ __forceinline__ void cp_commit() {
    asm volatile("cp.async.commit_group;" ::: "memory");
}
template <int N>
__device__ __forceinline__ void cp_wait() {
    asm volatile("cp.async.wait_group %0;" :: "n"(N) : "memory");
}

// ---------------------------------------------------------------------------
// 0) index dtype detection (int32 vs int64)
// ---------------------------------------------------------------------------
__global__ void detect_kernel(const void* __restrict__ ei) {
    if (threadIdx.x == 0) {
        const long long* p = (const long long*)ei;
        int is32 = 0;
        #pragma unroll 1
        for (int i = 0; i < 64; ++i) {
            long long v = p[i];
            if (v < 0 || v >= N_NODES) { is32 = 1; break; }
        }
        g_is32 = is32;
    }
}
__device__ __forceinline__ int load_idx(const void* p, long long i, int is32) {
    return is32 ? ((const int*)p)[i] : (int)((const long long*)p)[i];
}

// ---------------------------------------------------------------------------
// 1) weight prep (same layout as R4 — verified)
// ---------------------------------------------------------------------------
__global__ void wprep_kernel(const float* __restrict__ wrel,
                             const float* __restrict__ wself) {
    int gid = blockIdx.x * blockDim.x + threadIdx.x;
    if (gid >= NMAT * 8 * 2048) return;
    int j  = gid & 1;
    int l  = (gid >> 1) & 31;
    int nf = (gid >> 6) & 15;
    int s  = (gid >> 10) & 1;
    int kk = (gid >> 11) & 7;
    int r  = gid >> 14;
    int t = l & 3, g = l >> 2;
    int n  = nf * 8 + g;
    int k0 = kk * 16 + t * 2 + (j ? 8 : 0);

    float w0, w1;
    if (r < 8) {
        w0 = wrel[((size_t)r * 128 + k0) * 128 + n];
        w1 = wrel[((size_t)r * 128 + k0 + 1) * 128 + n];
    } else {
        w0 = wself[(size_t)k0 * 128 + n];
        w1 = wself[(size_t)(k0 + 1) * 128 + n];
    }
    uint32_t h, lo;
    split2(make_float2(w0, w1), h, lo);
    g_wB[gid] = s ? lo : h;
}

// ---------------------------------------------------------------------------
// 2) zero deg + hist
// ---------------------------------------------------------------------------
__global__ void zero2_kernel() {
    int i = blockIdx.x * blockDim.x + threadIdx.x;
    if (i < N_NODES * NREL) g_deg[i] = 0;
    if (i < NKEY) g_hist[i] = 0;
}

// ---------------------------------------------------------------------------
// 3) degree + bucket histogram
// ---------------------------------------------------------------------------
__global__ void deg_hist_kernel(const void* __restrict__ ei,
                                const void* __restrict__ et) {
    int e = blockIdx.x * blockDim.x + threadIdx.x;
    if (e >= NEDGES) return;
    int is32 = g_is32;
    int dst = load_idx(ei, (long long)NEDGES + e, is32);
    int r   = load_idx(et, e, is32);
    atomicAdd(&g_deg[dst * NREL + r], 1);
    atomicAdd(&g_hist[(dst >> 6) * 3 + r / 3], 1);
}

__global__ void inv_kernel() {
    int i = blockIdx.x * blockDim.x + threadIdx.x;
    if (i >= N_NODES * NREL) return;
    int d = g_deg[i];
    g_inv[i] = 1.0f / (float)(d > 1 ? d : 1);
}

// ---------------------------------------------------------------------------
// 4) exclusive scan over NKEY buckets (single block, 1024 threads)
// ---------------------------------------------------------------------------
#define SCAN_C ((NKEY + 1023) / 1024)
__global__ __launch_bounds__(1024) void scan_kernel() {
    __shared__ int part[1024];
    int t = threadIdx.x;
    int base = t * SCAN_C;
    int loc[SCAN_C];
    int s = 0;
    #pragma unroll
    for (int i = 0; i < SCAN_C; ++i) {
        int idx = base + i;
        int v = (idx < NKEY) ? g_hist[idx] : 0;
        loc[i] = s;
        s += v;
    }
    part[t] = s;
    __syncthreads();
    for (int d = 1; d < 1024; d <<= 1) {
        int v = part[t];
        int u = (t >= d) ? part[t - d] : 0;
        __syncthreads();
        part[t] = v + u;
        __syncthreads();
    }
    int excl = (t > 0) ? part[t - 1] : 0;
    #pragma unroll
    for (int i = 0; i < SCAN_C; ++i) {
        int idx = base + i;
        if (idx < NKEY) {
            int o = excl + loc[i];
            g_off[idx] = o;
            g_cursor[idx] = o;
        }
    }
    if (t == 1023) g_off[NKEY] = part[1023];
}

// ---------------------------------------------------------------------------
// 5) sort-scatter edges into buckets (packed record + pre-scaled weight)
// ---------------------------------------------------------------------------
__global__ void sortsc_kernel(const void* __restrict__ ei,
                              const void* __restrict__ et) {
    int e = blockIdx.x * blockDim.x + threadIdx.x;
    if (e >= NEDGES) return;
    int is32 = g_is32;
    int src = load_idx(ei, e, is32);
    int dst = load_idx(ei, (long long)NEDGES + e, is32);
    int r   = load_idx(et, e, is32);
    int key = (dst >> 6) * 3 + r / 3;
    int pos = atomicAdd(&g_cursor[key], 1);
    float sc = g_inv[dst * NREL + r];
    uint32_t packed = (uint32_t)src | ((uint32_t)(r % 3) << 17)
                    | ((uint32_t)(dst & 63) << 19);
    g_esort[pos] = make_uint2(packed, __float_as_uint(sc));
}

// ---------------------------------------------------------------------------
// 6) fused kernel: per 64-dst-node tile — aggregate (3 rel-groups), convert
//    to bf16 hi/lo fragments in-place, mma over all 9 mats, store out+bias.
//    Dynamic SMEM: hF 96KB + sB 16KB = 112KB.
// ---------------------------------------------------------------------------
__global__ __launch_bounds__(256) void fused_kernel(
    const float* __restrict__ x,
    const float* __restrict__ bias,
    float* __restrict__ out)
{
    extern __shared__ char dyn[];
    float*    hF = (float*)dyn;                       // [3][64][128] f32
    uint32_t* sB = (uint32_t*)(dyn + 3*64*128*4);     // [2][2][16][32][2] u32

    const int tid  = threadIdx.x;
    const int wid  = tid >> 5;
    const int lane = tid & 31;
    const int gq   = lane >> 2;        // group-of-4 (row within fragment)
    const int tq   = lane & 3;         // quad-pair (col within fragment)
    const int wm   = wid & 3;
    const int wn   = wid >> 2;
    const int m0   = blockIdx.x * MTILE;

    const uint32_t sB0 = smem_u32(sB);

    // prefetch B chunk 0
    {
        const char* src = (const char*)g_wB;
        cp16(sB0 + tid * 16, src + tid * 16);
        cp16(sB0 + 4096 + tid * 16, src + 4096 + tid * 16);
        cp_commit();
    }

    float acc[32];
    #pragma unroll
    for (int i = 0; i < 32; ++i) acc[i] = 0.f;

    #pragma unroll 1
    for (int g = 0; g < 3; ++g) {
        // ---- zero h slices 0,1; slice 2: zero (g<2) or fill with x (g==2)
        for (int i = tid; i < 2 * 64 * 128; i += 256) hF[i] = 0.f;
        if (g < 2) {
            for (int i = tid; i < 64 * 128; i += 256) hF[2 * 8192 + i] = 0.f;
        } else {
            for (int i = tid; i < 64 * 32; i += 256) {
                int n = i >> 5, kq = (i & 31) * 4;
                float4 v = make_float4(0.f, 0.f, 0.f, 0.f);
                if (m0 + n < N_NODES)
                    v = *(const float4*)(x + (size_t)(m0 + n) * DIM + kq);
                *(float4*)(hF + 2 * 8192 + n * 128 + kq) = v;
            }
        }
        __syncthreads();

        // ---- gather: one warp per edge, smem atomics into hF
        {
            const int key = blockIdx.x * 3 + g;
            const int beg = g_off[key], end = g_off[key + 1];
            for (int e = beg + wid; e < end; e += 8) {
                uint2 rec = g_esort[e];
                uint32_t p = rec.x;
                float sc = __uint_as_float(rec.y);
                int src = p & 0x1FFFF;
                int ri  = (p >> 17) & 3;
                int dl  = (p >> 19) & 63;
                const float4 v = *((const float4*)(x + (size_t)src * DIM) + lane);
                float* hp = hF + ((ri * 64 + dl) << 7) + lane * 4;
                atomicAdd(hp + 0, v.x * sc);
                atomicAdd(hp + 1, v.y * sc);
                atomicAdd(hp + 2, v.z * sc);
                atomicAdd(hp + 3, v.w * sc);
            }
        }
        __syncthreads();

        // ---- convert each slice in-place f32 -> bf16 hi/lo fragments
        #pragma unroll 1
        for (int j = 0; j < 3; ++j) {
            float* S = hF + j * 8192;
            uint32_t outv[4][8];
            #pragma unroll
            for (int s = 0; s < 4; ++s) {
                int idx = (tid >> 5) + 8 * s;       // 0..31
                int mf = idx >> 3, kk = idx & 7;
                int row0 = mf * 16 + gq, row1 = row0 + 8;
                int c0 = kk * 16 + 2 * tq, c2 = c0 + 8;
                float2 p00 = *(const float2*)(S + row0 * 128 + c0);
                float2 p10 = *(const float2*)(S + row1 * 128 + c0);
                float2 p01 = *(const float2*)(S + row0 * 128 + c2);
                float2 p11 = *(const float2*)(S + row1 * 128 + c2);
                split2(p00, outv[s][0], outv[s][4]);
                split2(p10, outv[s][1], outv[s][5]);
                split2(p01, outv[s][2], outv[s][6]);
                split2(p11, outv[s][3], outv[s][7]);
            }
            __syncthreads();
            uint32_t* fr = (uint32_t*)S;
            #pragma unroll
            for (int s = 0; s < 4; ++s) {
                int idx = (tid >> 5) + 8 * s;
                uint32_t* dst = fr + ((size_t)idx * 32 + lane) * 8;
                *(uint4*)(dst + 0) = make_uint4(outv[s][0], outv[s][1], outv[s][2], outv[s][3]);
                *(uint4*)(dst + 4) = make_uint4(outv[s][4], outv[s][5], outv[s][6], outv[s][7]);
            }
            __syncthreads();
        }

        // ---- mma over this group's 24 chunks (3 mats x 8 kfrags)
        #pragma unroll 1
        for (int local = 0; local < 24; ++local) {
            const int cg = g * 24 + local;
            cp_wait<0>();
            __syncthreads();
            if (cg + 1 < NCHUNK) {
                uint32_t sb = sB0 + ((cg + 1) & 1) * 8192;
                const char* src = (const char*)(g_wB + (size_t)(cg + 1) * 2048);
                cp16(sb + tid * 16, src + tid * 16);
                cp16(sb + 4096 + tid * 16, src + 4096 + tid * 16);
                cp_commit();
            }
            const int buf = cg & 1;
            const int jj = local >> 3;
            const int kk = local & 7;
            const uint32_t* fr = (const uint32_t*)(hF + jj * 8192);
            const uint32_t* ab = fr + ((size_t)(wm * 8 + kk) * 32 + lane) * 8;
            uint4 ah = *(const uint4*)(ab + 0);
            uint4 al = *(const uint4*)(ab + 4);

            const uint32_t* Bb = sB + buf * 2048;
            #pragma unroll
            for (int nf = 0; nf < 8; ++nf) {
                const int gnf = wn * 8 + nf;
                uint2 bh = *(const uint2*)(Bb + ((size_t)gnf * 32 + lane) * 2);
                uint2 bl = *(const uint2*)(Bb + 1024 + ((size_t)gnf * 32 + lane) * 2);
                float* c = &acc[nf * 4];
                mma_bf16(c, ah.x, ah.y, ah.z, ah.w, bh.x, bh.y);
                mma_bf16(c, al.x, al.y, al.z, al.w, bh.x, bh.y);
                mma_bf16(c, ah.x, ah.y, ah.z, ah.w, bl.x, bl.y);
            }
        }
        __syncthreads();   // fragments free before next group's zero
    }

    // ---- epilogue: out = acc + bias
    const int row0 = m0 + wm * 16 + gq;
    const int row1 = row0 + 8;
    #pragma unroll
    for (int nf = 0; nf < 8; ++nf) {
        const int col = wn * 64 + nf * 8 + 2 * tq;
        float2 bv = *(const float2*)(bias + col);
        if (row0 < N_NODES)
            *(float2*)(out + (size_t)row0 * DIM + col) =
                make_float2(acc[nf * 4 + 0] + bv.x, acc[nf * 4 + 1] + bv.y);
        if (row1 < N_NODES)
            *(float2*)(out + (size_t)row1 * DIM + col) =
                make_float2(acc[nf * 4 + 2] + bv.x, acc[nf * 4 + 3] + bv.y);
    }
}

// ---------------------------------------------------------------------------
// launch
// ---------------------------------------------------------------------------
extern "C" void kernel_launch(void* const* d_in, const int* in_sizes, int n_in,
                              void* d_out, int out_size) {
    const float* x     = (const float*)d_in[0];
    const void*  ei    = d_in[1];
    const void*  et    = d_in[2];
    const float* wrel  = (const float*)d_in[3];
    const float* wself = (const float*)d_in[4];
    const float* bias  = (const float*)d_in[5];
    float*       out   = (float*)d_out;

    static bool attr_set = false;
    if (!attr_set) {
        cudaFuncSetAttribute(fused_kernel,
                             cudaFuncAttributeMaxDynamicSharedMemorySize,
                             3 * 64 * 128 * 4 + 16384);
        attr_set = true;
    }

    detect_kernel<<<1, 32>>>(ei);
    wprep_kernel<<<(NMAT * 8 * 2048 + 255) / 256, 256>>>(wrel, wself);
    zero2_kernel<<<(N_NODES * NREL + 255) / 256, 256>>>();
    deg_hist_kernel<<<(NEDGES + 255) / 256, 256>>>(ei, et);
    inv_kernel<<<(N_NODES * NREL + 255) / 256, 256>>>();
    scan_kernel<<<1, 1024>>>();
    sortsc_kernel<<<(NEDGES + 255) / 256, 256>>>(ei, et);
    fused_kernel<<<NTILE, 256, 3 * 64 * 128 * 4 + 16384>>>(x, bias, out);
}

// round 6
// speedup vs baseline: 1.2029x; 1.2029x over previous
#include <cuda_runtime.h>
#include <cuda_bf16.h>
#include <cstdint>

#define N_NODES 100000
#define DIM     128
#define NREL    8
#define NEDGES  625000
#define NMAT    9
#define MTILE   128
#define NCHUNK  (NMAT * 8)           // 72 B chunks of 8KB

// ---------------------------------------------------------------------------
// Device globals
// ---------------------------------------------------------------------------
__device__ float    g_y[(size_t)NREL * N_NODES * DIM];   // 409.6 MB
__device__ int      g_deg[N_NODES * NREL];
__device__ float    g_inv[N_NODES * NREL];
__device__ int      g_is32;
__device__ uint32_t g_wB[NMAT * 8 * 2048];               // 576 KB packed B frags

// ---------------------------------------------------------------------------
// helpers
// ---------------------------------------------------------------------------
__device__ __forceinline__ uint32_t smem_u32(const void* p) {
    uint32_t a;
    asm("{ .reg .u64 t; cvta.to.shared.u64 t, %1; cvt.u32.u64 %0, t; }"
        : "=r"(a) : "l"(p));
    return a;
}
__device__ __forceinline__ uint32_t pack_bf2(__nv_bfloat16 lo, __nv_bfloat16 hi) {
    return (uint32_t)__bfloat16_as_ushort(lo) | ((uint32_t)__bfloat16_as_ushort(hi) << 16);
}
__device__ __forceinline__ void split2(float2 v, uint32_t& h, uint32_t& l) {
    __nv_bfloat16 h0 = __float2bfloat16(v.x);
    __nv_bfloat16 h1 = __float2bfloat16(v.y);
    __nv_bfloat16 l0 = __float2bfloat16(v.x - __bfloat162float(h0));
    __nv_bfloat16 l1 = __float2bfloat16(v.y - __bfloat162float(h1));
    h = pack_bf2(h0, h1);
    l = pack_bf2(l0, l1);
}
__device__ __forceinline__ void mma_bf16(float* c, uint32_t a0, uint32_t a1,
                                         uint32_t a2, uint32_t a3,
                                         uint32_t b0, uint32_t b1) {
    asm volatile(
        "mma.sync.aligned.m16n8k16.row.col.f32.bf16.bf16.f32 "
        "{%0,%1,%2,%3}, {%4,%5,%6,%7}, {%8,%9}, {%0,%1,%2,%3};"
        : "+f"(c[0]), "+f"(c[1]), "+f"(c[2]), "+f"(c[3])
        : "r"(a0), "r"(a1), "r"(a2), "r"(a3), "r"(b0), "r"(b1));
}
__device__ __forceinline__ void cp16(uint32_t smem_dst, const void* gsrc) {
    asm volatile("cp.async.cg.shared.global [%0], [%1], 16;"
                 :: "r"(smem_dst), "l"(gsrc));
}
__device__ __forceinline__ void cp_commit() {
    asm volatile("cp.async.commit_group;" ::: "memory");
}
template <int N>
__device__ __forceinline__ void cp_wait() {
    asm volatile("cp.async.wait_group %0;" :: "n"(N) : "memory");
}

// ---------------------------------------------------------------------------
// 0) index dtype detection (int32 vs int64)
// ---------------------------------------------------------------------------
__global__ void detect_kernel(const void* __restrict__ ei) {
    if (threadIdx.x == 0) {
        const long long* p = (const long long*)ei;
        int is32 = 0;
        #pragma unroll 1
        for (int i = 0; i < 64; ++i) {
            long long v = p[i];
            if (v < 0 || v >= N_NODES) { is32 = 1; break; }
        }
        g_is32 = is32;
    }
}
__device__ __forceinline__ int load_idx(const void* p, long long i, int is32) {
    return is32 ? ((const int*)p)[i] : (int)((const long long*)p)[i];
}

// ---------------------------------------------------------------------------
// 1) weight prep: pack W (fp32 [mat][k][n]) into per-fragment bf16 hi/lo chunks
// ---------------------------------------------------------------------------
__global__ void wprep_kernel(const float* __restrict__ wrel,
                             const float* __restrict__ wself) {
    int gid = blockIdx.x * blockDim.x + threadIdx.x;
    if (gid >= NMAT * 8 * 2048) return;
    int j  = gid & 1;
    int l  = (gid >> 1) & 31;
    int nf = (gid >> 6) & 15;
    int s  = (gid >> 10) & 1;
    int kk = (gid >> 11) & 7;
    int r  = gid >> 14;
    int t = l & 3, g = l >> 2;
    int n  = nf * 8 + g;
    int k0 = kk * 16 + t * 2 + (j ? 8 : 0);

    float w0, w1;
    if (r < 8) {
        w0 = wrel[((size_t)r * 128 + k0) * 128 + n];
        w1 = wrel[((size_t)r * 128 + k0 + 1) * 128 + n];
    } else {
        w0 = wself[(size_t)k0 * 128 + n];
        w1 = wself[(size_t)(k0 + 1) * 128 + n];
    }
    uint32_t h, lo;
    split2(make_float2(w0, w1), h, lo);
    g_wB[gid] = s ? lo : h;
}

// ---------------------------------------------------------------------------
// 2) degree
// ---------------------------------------------------------------------------
__global__ void zero_deg_kernel() {
    int i = blockIdx.x * blockDim.x + threadIdx.x;
    if (i < N_NODES * NREL) g_deg[i] = 0;
}
__global__ void deg_kernel(const void* __restrict__ ei, const void* __restrict__ et) {
    int e = blockIdx.x * blockDim.x + threadIdx.x;
    if (e >= NEDGES) return;
    int is32 = g_is32;
    int dst = load_idx(ei, (long long)NEDGES + e, is32);
    int r   = load_idx(et, e, is32);
    atomicAdd(&g_deg[dst * NREL + r], 1);
}
__global__ void inv_kernel() {
    int i = blockIdx.x * blockDim.x + threadIdx.x;
    if (i >= N_NODES * NREL) return;
    int d = g_deg[i];
    g_inv[i] = 1.0f / (float)(d > 1 ? d : 1);
}

// ---------------------------------------------------------------------------
// 3) xw kernel (MTILE=128): per block of 128 nodes compute y_r = x@W_r (r<8)
//    and out = x@W_self + bias (r==8). 8 warps, warp tile m16 x n128.
//    Dynamic smem: sA 64KB (fragments hi/lo) + sB 16KB (double buffer) = 80KB.
// ---------------------------------------------------------------------------
__global__ __launch_bounds__(256, 2) void xw_kernel(
    const float* __restrict__ x,
    const float* __restrict__ bias,
    float* __restrict__ out)
{
    extern __shared__ char dyn[];
    uint32_t* sA = (uint32_t*)dyn;            // [2][8][8][32][4] u32 = 64KB
    uint32_t* sB = (uint32_t*)(dyn + 65536);  // [2][2][16][32][2] u32 = 16KB

    const int tid  = threadIdx.x;
    const int wid  = tid >> 5;
    const int lane = tid & 31;
    const int gq   = lane >> 2;
    const int tq   = lane & 3;
    const int m0   = blockIdx.x * MTILE;

    const uint32_t sB0 = smem_u32(sB);

    // ---- prefetch B chunk 0
    {
        const char* src = (const char*)g_wB;
        cp16(sB0 + tid * 16, src + tid * 16);
        cp16(sB0 + 4096 + tid * 16, src + 4096 + tid * 16);
        cp_commit();
    }

    // ---- fill A fragments (hi/lo): warp wid owns mfrag wid
    {
        const int row0 = m0 + wid * 16 + gq;
        const int row1 = row0 + 8;
        const bool v0 = row0 < N_NODES, v1 = row1 < N_NODES;
        const float* xr0 = x + (size_t)row0 * DIM;
        const float* xr1 = x + (size_t)row1 * DIM;
        #pragma unroll
        for (int kk = 0; kk < 8; ++kk) {
            int c0 = kk * 16 + 2 * tq;
            int c2 = c0 + 8;
            float2 z = make_float2(0.f, 0.f);
            float2 p00 = v0 ? *(const float2*)(xr0 + c0) : z;
            float2 p10 = v1 ? *(const float2*)(xr1 + c0) : z;
            float2 p01 = v0 ? *(const float2*)(xr0 + c2) : z;
            float2 p11 = v1 ? *(const float2*)(xr1 + c2) : z;
            uint32_t h0, l0, h1, l1, h2, l2, h3, l3;
            split2(p00, h0, l0);
            split2(p10, h1, l1);
            split2(p01, h2, l2);
            split2(p11, h3, l3);
            uint32_t* d0 = sA + ((size_t)(wid * 8 + kk) * 32 + lane) * 4;
            *(uint4*)d0 = make_uint4(h0, h1, h2, h3);
            *(uint4*)(d0 + 8192) = make_uint4(l0, l1, l2, l3);
        }
    }
    __syncthreads();

    float acc[64];
    #pragma unroll
    for (int i = 0; i < 64; ++i) acc[i] = 0.f;

    const int row0 = m0 + wid * 16 + gq;
    const int row1 = row0 + 8;

    #pragma unroll 1
    for (int cg = 0; cg < NCHUNK; ++cg) {
        cp_wait<0>();
        __syncthreads();   // chunk cg resident; previous chunk fully consumed

        if (cg + 1 < NCHUNK) {
            uint32_t sb = sB0 + ((cg + 1) & 1) * 8192;
            const char* src = (const char*)(g_wB + (size_t)(cg + 1) * 2048);
            cp16(sb + tid * 16, src + tid * 16);
            cp16(sb + 4096 + tid * 16, src + 4096 + tid * 16);
            cp_commit();
        }

        const int buf = cg & 1;
        const int kk  = cg & 7;
        const uint32_t* ab = sA + ((size_t)(wid * 8 + kk) * 32 + lane) * 4;
        uint4 ah = *(const uint4*)ab;
        uint4 al = *(const uint4*)(ab + 8192);

        const uint32_t* Bb = sB + buf * 2048;
        #pragma unroll
        for (int nf = 0; nf < 16; ++nf) {
            uint2 bh = *(const uint2*)(Bb + ((size_t)nf * 32 + lane) * 2);
            uint2 bl = *(const uint2*)(Bb + 1024 + ((size_t)nf * 32 + lane) * 2);
            float* c = &acc[nf * 4];
            mma_bf16(c, ah.x, ah.y, ah.z, ah.w, bh.x, bh.y);
            mma_bf16(c, al.x, al.y, al.z, al.w, bh.x, bh.y);
            mma_bf16(c, ah.x, ah.y, ah.z, ah.w, bl.x, bl.y);
        }

        // ---- epilogue at end of each relation
        if (kk == 7) {
            const int r = cg >> 3;
            if (r < 8) {
                float* y0 = g_y + ((size_t)r * N_NODES + row0) * DIM;
                float* y1 = g_y + ((size_t)r * N_NODES + row1) * DIM;
                #pragma unroll
                for (int nf = 0; nf < 16; ++nf) {
                    const int col = nf * 8 + 2 * tq;
                    if (row0 < N_NODES)
                        __stcs((float2*)(y0 + col),
                               make_float2(acc[nf * 4 + 0], acc[nf * 4 + 1]));
                    if (row1 < N_NODES)
                        __stcs((float2*)(y1 + col),
                               make_float2(acc[nf * 4 + 2], acc[nf * 4 + 3]));
                }
            } else {
                #pragma unroll
                for (int nf = 0; nf < 16; ++nf) {
                    const int col = nf * 8 + 2 * tq;
                    float2 bv = *(const float2*)(bias + col);
                    if (row0 < N_NODES)
                        *(float2*)(out + (size_t)row0 * DIM + col) =
                            make_float2(acc[nf * 4 + 0] + bv.x, acc[nf * 4 + 1] + bv.y);
                    if (row1 < N_NODES)
                        *(float2*)(out + (size_t)row1 * DIM + col) =
                            make_float2(acc[nf * 4 + 2] + bv.x, acc[nf * 4 + 3] + bv.y);
                }
            }
            #pragma unroll
            for (int i = 0; i < 64; ++i) acc[i] = 0.f;
        }
    }
}

// ---------------------------------------------------------------------------
// 4) scatter: one warp per edge: out[dst] += y[rel][src] * inv_deg[dst,rel]
// ---------------------------------------------------------------------------
__global__ void scatter_kernel(const void* __restrict__ ei,
                               const void* __restrict__ et,
                               float* __restrict__ out) {
    int gtid = blockIdx.x * blockDim.x + threadIdx.x;
    int e    = gtid >> 5;
    int lane = gtid & 31;
    if (e >= NEDGES) return;

    int is32 = g_is32;
    int src = load_idx(ei, e, is32);
    int dst = load_idx(ei, (long long)NEDGES + e, is32);
    int r   = load_idx(et, e, is32);
    float s = g_inv[dst * NREL + r];

    const float4 v = __ldcs((const float4*)(g_y + ((size_t)r * N_NODES + src) * DIM) + lane);
    float* o = out + (size_t)dst * DIM + lane * 4;
    asm volatile("red.global.add.v4.f32 [%0], {%1,%2,%3,%4};"
                 :: "l"(o), "f"(v.x * s), "f"(v.y * s), "f"(v.z * s), "f"(v.w * s)
                 : "memory");
}

// ---------------------------------------------------------------------------
// launch
// ---------------------------------------------------------------------------
extern "C" void kernel_launch(void* const* d_in, const int* in_sizes, int n_in,
                              void* d_out, int out_size) {
    const float* x     = (const float*)d_in[0];
    const void*  ei    = d_in[1];
    const void*  et    = d_in[2];
    const float* wrel  = (const float*)d_in[3];
    const float* wself = (const float*)d_in[4];
    const float* bias  = (const float*)d_in[5];
    float*       out   = (float*)d_out;

    static bool attr_set = false;
    if (!attr_set) {
        cudaFuncSetAttribute(xw_kernel,
                             cudaFuncAttributeMaxDynamicSharedMemorySize,
                             65536 + 16384);
        attr_set = true;
    }

    detect_kernel<<<1, 32>>>(ei);
    wprep_kernel<<<(NMAT * 8 * 2048 + 255) / 256, 256>>>(wrel, wself);
    zero_deg_kernel<<<(N_NODES * NREL + 255) / 256, 256>>>();
    deg_kernel<<<(NEDGES + 255) / 256, 256>>>(ei, et);
    inv_kernel<<<(N_NODES * NREL + 255) / 256, 256>>>();
    xw_kernel<<<(N_NODES + MTILE - 1) / MTILE, 256, 65536 + 16384>>>(x, bias, out);
    scatter_kernel<<<((size_t)NEDGES * 32 + 255) / 256, 256>>>(ei, et, out);
}

// round 7
// speedup vs baseline: 1.5961x; 1.3269x over previous
#include <cuda_runtime.h>
#include <cuda_fp16.h>
#include <cstdint>

#define N_NODES 100000
#define DIM     128
#define NREL    8
#define NEDGES  625000
#define NMAT    9
#define MTILE   64
#define NCHUNK  (NMAT * 8)           // 72 B chunks of 8KB

// ---------------------------------------------------------------------------
// Device globals
// ---------------------------------------------------------------------------
__device__ float    g_y[(size_t)NREL * N_NODES * DIM];   // 409.6 MB
__device__ int      g_deg[N_NODES * NREL];
__device__ float    g_inv[N_NODES * NREL];
__device__ int      g_is32;
// Pre-packed B fragments (fp16 hi/lo): per (mat,kfrag) an 8KB chunk:
// [split 2][nfrag 16][lane 32][reg 2] u32.  chunk cg = mat*8+kfrag.
__device__ uint32_t g_wB[NMAT * 8 * 2048];               // 576 KB

// ---------------------------------------------------------------------------
// helpers
// ---------------------------------------------------------------------------
__device__ __forceinline__ uint32_t smem_u32(const void* p) {
    uint32_t a;
    asm("{ .reg .u64 t; cvta.to.shared.u64 t, %1; cvt.u32.u64 %0, t; }"
        : "=r"(a) : "l"(p));
    return a;
}
__device__ __forceinline__ uint32_t pack_h2(__half a, __half b) {
    return (uint32_t)__half_as_ushort(a) | ((uint32_t)__half_as_ushort(b) << 16);
}
// fp16 pack of float2 (no split)
__device__ __forceinline__ uint32_t cvt2(float2 v) {
    return pack_h2(__float2half_rn(v.x), __float2half_rn(v.y));
}
// fp16 hi/lo split of float2
__device__ __forceinline__ void split2h(float2 v, uint32_t& h, uint32_t& l) {
    __half h0 = __float2half_rn(v.x);
    __half h1 = __float2half_rn(v.y);
    __half l0 = __float2half_rn(v.x - __half2float(h0));
    __half l1 = __float2half_rn(v.y - __half2float(h1));
    h = pack_h2(h0, h1);
    l = pack_h2(l0, l1);
}
__device__ __forceinline__ void mma_f16(float* c, uint32_t a0, uint32_t a1,
                                        uint32_t a2, uint32_t a3,
                                        uint32_t b0, uint32_t b1) {
    asm volatile(
        "mma.sync.aligned.m16n8k16.row.col.f32.f16.f16.f32 "
        "{%0,%1,%2,%3}, {%4,%5,%6,%7}, {%8,%9}, {%0,%1,%2,%3};"
        : "+f"(c[0]), "+f"(c[1]), "+f"(c[2]), "+f"(c[3])
        : "r"(a0), "r"(a1), "r"(a2), "r"(a3), "r"(b0), "r"(b1));
}
__device__ __forceinline__ void cp16(uint32_t smem_dst, const void* gsrc) {
    asm volatile("cp.async.cg.shared.global [%0], [%1], 16;"
                 :: "r"(smem_dst), "l"(gsrc));
}
__device__ __forceinline__ void cp_commit() {
    asm volatile("cp.async.commit_group;" ::: "memory");
}
template <int N>
__device__ __forceinline__ void cp_wait() {
    asm volatile("cp.async.wait_group %0;" :: "n"(N) : "memory");
}

// ---------------------------------------------------------------------------
// 0) index dtype detection (int32 vs int64)
// ---------------------------------------------------------------------------
__global__ void detect_kernel(const void* __restrict__ ei) {
    if (threadIdx.x == 0) {
        const long long* p = (const long long*)ei;
        int is32 = 0;
        #pragma unroll 1
        for (int i = 0; i < 64; ++i) {
            long long v = p[i];
            if (v < 0 || v >= N_NODES) { is32 = 1; break; }
        }
        g_is32 = is32;
    }
}
__device__ __forceinline__ int load_idx(const void* p, long long i, int is32) {
    return is32 ? ((const int*)p)[i] : (int)((const long long*)p)[i];
}

// ---------------------------------------------------------------------------
// 1) weight prep: pack W (fp32 [mat][k][n]) into fp16 hi/lo fragment chunks
//    linear index = r<<14 | kk<<11 | s<<10 | nf<<6 | lane<<1 | j
// ---------------------------------------------------------------------------
__global__ void wprep_kernel(const float* __restrict__ wrel,
                             const float* __restrict__ wself) {
    int gid = blockIdx.x * blockDim.x + threadIdx.x;
    if (gid >= NMAT * 8 * 2048) return;
    int j  = gid & 1;
    int l  = (gid >> 1) & 31;
    int nf = (gid >> 6) & 15;
    int s  = (gid >> 10) & 1;
    int kk = (gid >> 11) & 7;
    int r  = gid >> 14;
    int t = l & 3, g = l >> 2;
    int n  = nf * 8 + g;
    int k0 = kk * 16 + t * 2 + (j ? 8 : 0);

    float w0, w1;
    if (r < 8) {
        w0 = wrel[((size_t)r * 128 + k0) * 128 + n];
        w1 = wrel[((size_t)r * 128 + k0 + 1) * 128 + n];
    } else {
        w0 = wself[(size_t)k0 * 128 + n];
        w1 = wself[(size_t)(k0 + 1) * 128 + n];
    }
    uint32_t h, lo;
    split2h(make_float2(w0, w1), h, lo);
    g_wB[gid] = s ? lo : h;
}

// ---------------------------------------------------------------------------
// 2) degree
// ---------------------------------------------------------------------------
__global__ void zero_deg_kernel() {
    int i = blockIdx.x * blockDim.x + threadIdx.x;
    if (i < N_NODES * NREL) g_deg[i] = 0;
}
__global__ void deg_kernel(const void* __restrict__ ei, const void* __restrict__ et) {
    int e = blockIdx.x * blockDim.x + threadIdx.x;
    if (e >= NEDGES) return;
    int is32 = g_is32;
    int dst = load_idx(ei, (long long)NEDGES + e, is32);
    int r   = load_idx(et, e, is32);
    atomicAdd(&g_deg[dst * NREL + r], 1);
}
__global__ void inv_kernel() {
    int i = blockIdx.x * blockDim.x + threadIdx.x;
    if (i >= N_NODES * NREL) return;
    int d = g_deg[i];
    g_inv[i] = 1.0f / (float)(d > 1 ? d : 1);
}

// ---------------------------------------------------------------------------
// 3) xw kernel (R4 schedule, fp16 2-product): per block of 64 nodes compute
//    y_r = x@W_r (r<8, into g_y) and out = x@W_self + bias (r==8).
//    8 warps: wm = wid&3 (M 16-rows), wn = wid>>2 (N 64-cols).
//    Static smem: sA 16KB (fp16 A frags) + sB 16KB (double buffer) = 32KB.
// ---------------------------------------------------------------------------
__global__ __launch_bounds__(256) void xw_kernel(
    const float* __restrict__ x,
    const float* __restrict__ bias,
    float* __restrict__ out)
{
    __shared__ uint32_t sA[4][8][32][4];      // [mfrag][kfrag][lane][reg] 16KB
    __shared__ uint32_t sB[2][2][16][32][2];  // [buf][split][nfrag][lane][reg] 16KB

    const int tid  = threadIdx.x;
    const int wid  = tid >> 5;
    const int lane = tid & 31;
    const int gq   = lane >> 2;
    const int tq   = lane & 3;
    const int wm   = wid & 3;
    const int wn   = wid >> 2;
    const int m0   = blockIdx.x * MTILE;

    // ---- prefetch B chunk 0
    {
        uint32_t sb = smem_u32(&sB[0][0][0][0][0]);
        const char* src = (const char*)g_wB;
        cp16(sb + tid * 16, src + tid * 16);
        cp16(sb + 4096 + tid * 16, src + 4096 + tid * 16);
        cp_commit();
    }

    // ---- fill A fragments (fp16, no split)
    {
        int mf  = wid & 3;
        int kk0 = (wid >> 2) * 4;
        int row0 = m0 + mf * 16 + gq;
        int row1 = row0 + 8;
        bool v0 = row0 < N_NODES, v1 = row1 < N_NODES;
        const float* xr0 = x + (size_t)row0 * DIM;
        const float* xr1 = x + (size_t)row1 * DIM;
        #pragma unroll
        for (int kk = kk0; kk < kk0 + 4; ++kk) {
            int c0 = kk * 16 + 2 * tq;
            int c2 = c0 + 8;
            float2 z = make_float2(0.f, 0.f);
            float2 p00 = v0 ? *(const float2*)(xr0 + c0) : z;
            float2 p10 = v1 ? *(const float2*)(xr1 + c0) : z;
            float2 p01 = v0 ? *(const float2*)(xr0 + c2) : z;
            float2 p11 = v1 ? *(const float2*)(xr1 + c2) : z;
            *(uint4*)&sA[mf][kk][lane][0] =
                make_uint4(cvt2(p00), cvt2(p10), cvt2(p01), cvt2(p11));
        }
    }
    __syncthreads();

    float acc[32];
    #pragma unroll
    for (int i = 0; i < 32; ++i) acc[i] = 0.f;

    const int row0 = m0 + wm * 16 + gq;
    const int row1 = row0 + 8;

    #pragma unroll 1
    for (int cg = 0; cg < NCHUNK; ++cg) {
        cp_wait<0>();
        __syncthreads();   // chunk cg resident; previous chunk fully consumed

        if (cg + 1 < NCHUNK) {
            uint32_t sb = smem_u32(&sB[(cg + 1) & 1][0][0][0][0]);
            const char* src = (const char*)(g_wB + (size_t)(cg + 1) * 2048);
            cp16(sb + tid * 16, src + tid * 16);
            cp16(sb + 4096 + tid * 16, src + 4096 + tid * 16);
            cp_commit();
        }

        const int buf = cg & 1;
        const int kk  = cg & 7;
        uint4 a = *(const uint4*)&sA[wm][kk][lane][0];

        #pragma unroll
        for (int nf = 0; nf < 8; ++nf) {
            const int gnf = wn * 8 + nf;
            uint2 bh = *(const uint2*)&sB[buf][0][gnf][lane][0];
            uint2 bl = *(const uint2*)&sB[buf][1][gnf][lane][0];
            float* c = &acc[nf * 4];
            mma_f16(c, a.x, a.y, a.z, a.w, bh.x, bh.y);
            mma_f16(c, a.x, a.y, a.z, a.w, bl.x, bl.y);
        }

        // ---- epilogue at end of each relation
        if (kk == 7) {
            const int r = cg >> 3;
            if (r < 8) {
                if (row0 < N_NODES) {
                    float* y0 = g_y + ((size_t)r * N_NODES + row0) * DIM + wn * 64;
                    #pragma unroll
                    for (int nf = 0; nf < 8; ++nf)
                        __stcs((float2*)(y0 + nf * 8 + 2 * tq),
                               make_float2(acc[nf * 4 + 0], acc[nf * 4 + 1]));
                }
                if (row1 < N_NODES) {
                    float* y1 = g_y + ((size_t)r * N_NODES + row1) * DIM + wn * 64;
                    #pragma unroll
                    for (int nf = 0; nf < 8; ++nf)
                        __stcs((float2*)(y1 + nf * 8 + 2 * tq),
                               make_float2(acc[nf * 4 + 2], acc[nf * 4 + 3]));
                }
            } else {
                #pragma unroll
                for (int nf = 0; nf < 8; ++nf) {
                    const int col = wn * 64 + nf * 8 + 2 * tq;
                    float2 bv = *(const float2*)(bias + col);
                    if (row0 < N_NODES)
                        *(float2*)(out + (size_t)row0 * DIM + col) =
                            make_float2(acc[nf * 4 + 0] + bv.x, acc[nf * 4 + 1] + bv.y);
                    if (row1 < N_NODES)
                        *(float2*)(out + (size_t)row1 * DIM + col) =
                            make_float2(acc[nf * 4 + 2] + bv.x, acc[nf * 4 + 3] + bv.y);
                }
            }
            #pragma unroll
            for (int i = 0; i < 32; ++i) acc[i] = 0.f;
        }
    }
}

// ---------------------------------------------------------------------------
// 4) scatter: one warp per edge: out[dst] += y[rel][src] * inv_deg[dst,rel]
// ---------------------------------------------------------------------------
__global__ void scatter_kernel(const void* __restrict__ ei,
                               const void* __restrict__ et,
                               float* __restrict__ out) {
    int gtid = blockIdx.x * blockDim.x + threadIdx.x;
    int e    = gtid >> 5;
    int lane = gtid & 31;
    if (e >= NEDGES) return;

    int is32 = g_is32;
    int src = load_idx(ei, e, is32);
    int dst = load_idx(ei, (long long)NEDGES + e, is32);
    int r   = load_idx(et, e, is32);
    float s = g_inv[dst * NREL + r];

    const float4 v = __ldcs((const float4*)(g_y + ((size_t)r * N_NODES + src) * DIM) + lane);
    float* o = out + (size_t)dst * DIM + lane * 4;
    asm volatile("red.global.add.v4.f32 [%0], {%1,%2,%3,%4};"
                 :: "l"(o), "f"(v.x * s), "f"(v.y * s), "f"(v.z * s), "f"(v.w * s)
                 : "memory");
}

// ---------------------------------------------------------------------------
// launch
// ---------------------------------------------------------------------------
extern "C" void kernel_launch(void* const* d_in, const int* in_sizes, int n_in,
                              void* d_out, int out_size) {
    const float* x     = (const float*)d_in[0];
    const void*  ei    = d_in[1];
    const void*  et    = d_in[2];
    const float* wrel  = (const float*)d_in[3];
    const float* wself = (const float*)d_in[4];
    const float* bias  = (const float*)d_in[5];
    float*       out   = (float*)d_out;

    detect_kernel<<<1, 32>>>(ei);
    wprep_kernel<<<(NMAT * 8 * 2048 + 255) / 256, 256>>>(wrel, wself);
    zero_deg_kernel<<<(N_NODES * NREL + 255) / 256, 256>>>();
    deg_kernel<<<(NEDGES + 255) / 256, 256>>>(ei, et);
    inv_kernel<<<(N_NODES * NREL + 255) / 256, 256>>>();
    xw_kernel<<<(N_NODES + MTILE - 1) / MTILE, 256>>>(x, bias, out);
    scatter_kernel<<<((size_t)NEDGES * 32 + 255) / 256, 256>>>(ei, et, out);
}

// round 8
// speedup vs baseline: 2.0577x; 1.2892x over previous
#include <cuda_runtime.h>
#include <cuda_fp16.h>
#include <cstdint>

#define N_NODES 100000
#define DIM     128
#define NREL    8
#define NEDGES  625000
#define NMAT    9
#define MTILE   64
#define NIT     (NMAT * 4)           // 36 iterations, 2 k-frag chunks each

// ---------------------------------------------------------------------------
// Device globals
// ---------------------------------------------------------------------------
__device__ __half   g_yh[(size_t)NREL * N_NODES * DIM]; // 204.8 MB fp16
__device__ int      g_deg[N_NODES * NREL];
__device__ float    g_inv[N_NODES * NREL];
__device__ int      g_is32;
// Pre-packed B fragments (fp16, single precision product):
// chunk cg = mat*8+kfrag, 4KB each: [nfrag 16][lane 32][reg 2] u32
__device__ uint32_t g_wB[NMAT * 8 * 1024];              // 288 KB

// ---------------------------------------------------------------------------
// helpers
// ---------------------------------------------------------------------------
__device__ __forceinline__ uint32_t smem_u32(const void* p) {
    uint32_t a;
    asm("{ .reg .u64 t; cvta.to.shared.u64 t, %1; cvt.u32.u64 %0, t; }"
        : "=r"(a) : "l"(p));
    return a;
}
__device__ __forceinline__ uint32_t pack_h2(__half a, __half b) {
    return (uint32_t)__half_as_ushort(a) | ((uint32_t)__half_as_ushort(b) << 16);
}
__device__ __forceinline__ uint32_t cvt2(float2 v) {
    return pack_h2(__float2half_rn(v.x), __float2half_rn(v.y));
}
__device__ __forceinline__ void mma_f16(float* c, uint32_t a0, uint32_t a1,
                                        uint32_t a2, uint32_t a3,
                                        uint32_t b0, uint32_t b1) {
    asm volatile(
        "mma.sync.aligned.m16n8k16.row.col.f32.f16.f16.f32 "
        "{%0,%1,%2,%3}, {%4,%5,%6,%7}, {%8,%9}, {%0,%1,%2,%3};"
        : "+f"(c[0]), "+f"(c[1]), "+f"(c[2]), "+f"(c[3])
        : "r"(a0), "r"(a1), "r"(a2), "r"(a3), "r"(b0), "r"(b1));
}
__device__ __forceinline__ void cp16(uint32_t smem_dst, const void* gsrc) {
    asm volatile("cp.async.cg.shared.global [%0], [%1], 16;"
                 :: "r"(smem_dst), "l"(gsrc));
}
__device__ __forceinline__ void cp_commit() {
    asm volatile("cp.async.commit_group;" ::: "memory");
}
template <int N>
__device__ __forceinline__ void cp_wait() {
    asm volatile("cp.async.wait_group %0;" :: "n"(N) : "memory");
}

// ---------------------------------------------------------------------------
// 0) index dtype detection (int32 vs int64)
// ---------------------------------------------------------------------------
__global__ void detect_kernel(const void* __restrict__ ei) {
    if (threadIdx.x == 0) {
        const long long* p = (const long long*)ei;
        int is32 = 0;
        #pragma unroll 1
        for (int i = 0; i < 64; ++i) {
            long long v = p[i];
            if (v < 0 || v >= N_NODES) { is32 = 1; break; }
        }
        g_is32 = is32;
    }
}
__device__ __forceinline__ int load_idx(const void* p, long long i, int is32) {
    return is32 ? ((const int*)p)[i] : (int)((const long long*)p)[i];
}

// ---------------------------------------------------------------------------
// 1) weight prep: pack W (fp32 [mat][k][n]) into fp16 fragment chunks
//    u32 index = cg*1024 + nf*64 + lane*2 + j,  cg = r*8 + kk
// ---------------------------------------------------------------------------
__global__ void wprep_kernel(const float* __restrict__ wrel,
                             const float* __restrict__ wself) {
    int gid = blockIdx.x * blockDim.x + threadIdx.x;
    if (gid >= NMAT * 8 * 1024) return;
    int j  = gid & 1;
    int l  = (gid >> 1) & 31;
    int nf = (gid >> 6) & 15;
    int kk = (gid >> 10) & 7;
    int r  = gid >> 13;
    int t = l & 3, g = l >> 2;
    int n  = nf * 8 + g;
    int k0 = kk * 16 + t * 2 + (j ? 8 : 0);

    float w0, w1;
    if (r < 8) {
        w0 = wrel[((size_t)r * 128 + k0) * 128 + n];
        w1 = wrel[((size_t)r * 128 + k0 + 1) * 128 + n];
    } else {
        w0 = wself[(size_t)k0 * 128 + n];
        w1 = wself[(size_t)(k0 + 1) * 128 + n];
    }
    g_wB[gid] = cvt2(make_float2(w0, w1));
}

// ---------------------------------------------------------------------------
// 2) degree
// ---------------------------------------------------------------------------
__global__ void zero_deg_kernel() {
    int i = blockIdx.x * blockDim.x + threadIdx.x;
    if (i < N_NODES * NREL) g_deg[i] = 0;
}
__global__ void deg_kernel(const void* __restrict__ ei, const void* __restrict__ et) {
    int e = blockIdx.x * blockDim.x + threadIdx.x;
    if (e >= NEDGES) return;
    int is32 = g_is32;
    int dst = load_idx(ei, (long long)NEDGES + e, is32);
    int r   = load_idx(et, e, is32);
    atomicAdd(&g_deg[dst * NREL + r], 1);
}
__global__ void inv_kernel() {
    int i = blockIdx.x * blockDim.x + threadIdx.x;
    if (i >= N_NODES * NREL) return;
    int d = g_deg[i];
    g_inv[i] = 1.0f / (float)(d > 1 ? d : 1);
}

// ---------------------------------------------------------------------------
// 3) xw kernel: per block of 64 nodes, y_r = x@W_r (r<8, fp16 into g_yh),
//    out = x@W_self + bias (r==8). Single-product fp16 mma.
//    36 iterations x 2 chunks (8KB) double-buffered.
//    Static smem: sA 16KB + sB 16KB = 32KB.
// ---------------------------------------------------------------------------
__global__ __launch_bounds__(256) void xw_kernel(
    const float* __restrict__ x,
    const float* __restrict__ bias,
    float* __restrict__ out)
{
    __shared__ uint32_t sA[4][8][32][4];      // [mfrag][kfrag][lane][reg] 16KB
    __shared__ uint32_t sB[2][2][16][32][2];  // [buf][chunk][nfrag][lane][reg] 16KB

    const int tid  = threadIdx.x;
    const int wid  = tid >> 5;
    const int lane = tid & 31;
    const int gq   = lane >> 2;
    const int tq   = lane & 3;
    const int wm   = wid & 3;
    const int wn   = wid >> 2;
    const int m0   = blockIdx.x * MTILE;

    // ---- prefetch iteration 0 (chunks 0,1 = 8KB)
    {
        uint32_t sb = smem_u32(&sB[0][0][0][0][0]);
        const char* src = (const char*)g_wB;
        cp16(sb + tid * 16, src + tid * 16);
        cp16(sb + 4096 + tid * 16, src + 4096 + tid * 16);
        cp_commit();
    }

    // ---- fill A fragments (fp16)
    {
        int mf  = wid & 3;
        int kk0 = (wid >> 2) * 4;
        int row0 = m0 + mf * 16 + gq;
        int row1 = row0 + 8;
        bool v0 = row0 < N_NODES, v1 = row1 < N_NODES;
        const float* xr0 = x + (size_t)row0 * DIM;
        const float* xr1 = x + (size_t)row1 * DIM;
        #pragma unroll
        for (int kk = kk0; kk < kk0 + 4; ++kk) {
            int c0 = kk * 16 + 2 * tq;
            int c2 = c0 + 8;
            float2 z = make_float2(0.f, 0.f);
            float2 p00 = v0 ? *(const float2*)(xr0 + c0) : z;
            float2 p10 = v1 ? *(const float2*)(xr1 + c0) : z;
            float2 p01 = v0 ? *(const float2*)(xr0 + c2) : z;
            float2 p11 = v1 ? *(const float2*)(xr1 + c2) : z;
            *(uint4*)&sA[mf][kk][lane][0] =
                make_uint4(cvt2(p00), cvt2(p10), cvt2(p01), cvt2(p11));
        }
    }
    __syncthreads();

    float acc[32];
    #pragma unroll
    for (int i = 0; i < 32; ++i) acc[i] = 0.f;

    const int row0 = m0 + wm * 16 + gq;
    const int row1 = row0 + 8;

    #pragma unroll 1
    for (int it = 0; it < NIT; ++it) {
        cp_wait<0>();
        __syncthreads();   // iteration's 2 chunks resident; previous consumed

        if (it + 1 < NIT) {
            uint32_t sb = smem_u32(&sB[(it + 1) & 1][0][0][0][0]);
            const char* src = (const char*)(g_wB + (size_t)(it + 1) * 2048);
            cp16(sb + tid * 16, src + tid * 16);
            cp16(sb + 4096 + tid * 16, src + 4096 + tid * 16);
            cp_commit();
        }

        const int buf = it & 1;
        const int kk0 = (it & 3) * 2;
        uint4 a0 = *(const uint4*)&sA[wm][kk0][lane][0];
        uint4 a1 = *(const uint4*)&sA[wm][kk0 + 1][lane][0];

        #pragma unroll
        for (int nf = 0; nf < 8; ++nf) {
            const int gnf = wn * 8 + nf;
            uint2 b0 = *(const uint2*)&sB[buf][0][gnf][lane][0];
            uint2 b1 = *(const uint2*)&sB[buf][1][gnf][lane][0];
            float* c = &acc[nf * 4];
            mma_f16(c, a0.x, a0.y, a0.z, a0.w, b0.x, b0.y);
            mma_f16(c, a1.x, a1.y, a1.z, a1.w, b1.x, b1.y);
        }

        // ---- epilogue at end of each relation (every 4 iterations)
        if ((it & 3) == 3) {
            const int r = it >> 2;
            if (r < 8) {
                if (row0 < N_NODES) {
                    __half* y0 = g_yh + ((size_t)r * N_NODES + row0) * DIM + wn * 64;
                    #pragma unroll
                    for (int nf = 0; nf < 8; ++nf) {
                        uint32_t p = pack_h2(__float2half_rn(acc[nf*4+0]),
                                             __float2half_rn(acc[nf*4+1]));
                        __stcs((float*)(y0 + nf * 8 + 2 * tq), __uint_as_float(p));
                    }
                }
                if (row1 < N_NODES) {
                    __half* y1 = g_yh + ((size_t)r * N_NODES + row1) * DIM + wn * 64;
                    #pragma unroll
                    for (int nf = 0; nf < 8; ++nf) {
                        uint32_t p = pack_h2(__float2half_rn(acc[nf*4+2]),
                                             __float2half_rn(acc[nf*4+3]));
                        __stcs((float*)(y1 + nf * 8 + 2 * tq), __uint_as_float(p));
                    }
                }
            } else {
                #pragma unroll
                for (int nf = 0; nf < 8; ++nf) {
                    const int col = wn * 64 + nf * 8 + 2 * tq;
                    float2 bv = *(const float2*)(bias + col);
                    if (row0 < N_NODES)
                        *(float2*)(out + (size_t)row0 * DIM + col) =
                            make_float2(acc[nf*4+0] + bv.x, acc[nf*4+1] + bv.y);
                    if (row1 < N_NODES)
                        *(float2*)(out + (size_t)row1 * DIM + col) =
                            make_float2(acc[nf*4+2] + bv.x, acc[nf*4+3] + bv.y);
                }
            }
            #pragma unroll
            for (int i = 0; i < 32; ++i) acc[i] = 0.f;
        }
    }
}

// ---------------------------------------------------------------------------
// 4) scatter: one warp per edge: out[dst] += y[rel][src] * inv_deg[dst,rel]
//    fp16 y reads (256B/row), fp32 vector reductions into out.
// ---------------------------------------------------------------------------
__global__ void scatter_kernel(const void* __restrict__ ei,
                               const void* __restrict__ et,
                               float* __restrict__ out) {
    int gtid = blockIdx.x * blockDim.x + threadIdx.x;
    int e    = gtid >> 5;
    int lane = gtid & 31;
    if (e >= NEDGES) return;

    int is32 = g_is32;
    int src = load_idx(ei, e, is32);
    int dst = load_idx(ei, (long long)NEDGES + e, is32);
    int r   = load_idx(et, e, is32);
    float s = g_inv[dst * NREL + r];

    const __half* yrow = g_yh + ((size_t)r * N_NODES + src) * DIM;
    uint32_t u0, u1;
    asm volatile("ld.global.cs.v2.u32 {%0,%1}, [%2];"
                 : "=r"(u0), "=r"(u1) : "l"(yrow + lane * 4));
    __half2 h01 = *reinterpret_cast<__half2*>(&u0);
    __half2 h23 = *reinterpret_cast<__half2*>(&u1);
    float2 f01 = __half22float2(h01);
    float2 f23 = __half22float2(h23);

    float* o = out + (size_t)dst * DIM + lane * 4;
    asm volatile("red.global.add.v4.f32 [%0], {%1,%2,%3,%4};"
                 :: "l"(o), "f"(f01.x * s), "f"(f01.y * s),
                    "f"(f23.x * s), "f"(f23.y * s)
                 : "memory");
}

// ---------------------------------------------------------------------------
// launch
// ---------------------------------------------------------------------------
extern "C" void kernel_launch(void* const* d_in, const int* in_sizes, int n_in,
                              void* d_out, int out_size) {
    const float* x     = (const float*)d_in[0];
    const void*  ei    = d_in[1];
    const void*  et    = d_in[2];
    const float* wrel  = (const float*)d_in[3];
    const float* wself = (const float*)d_in[4];
    const float* bias  = (const float*)d_in[5];
    float*       out   = (float*)d_out;

    detect_kernel<<<1, 32>>>(ei);
    wprep_kernel<<<(NMAT * 8 * 1024 + 255) / 256, 256>>>(wrel, wself);
    zero_deg_kernel<<<(N_NODES * NREL + 255) / 256, 256>>>();
    deg_kernel<<<(NEDGES + 255) / 256, 256>>>(ei, et);
    inv_kernel<<<(N_NODES * NREL + 255) / 256, 256>>>();
    xw_kernel<<<(N_NODES + MTILE - 1) / MTILE, 256>>>(x, bias, out);
    scatter_kernel<<<((size_t)NEDGES * 32 + 255) / 256, 256>>>(ei, et, out);
}